// round 2
// baseline (speedup 1.0000x reference)
#include <cuda_runtime.h>
#include <cuda_bf16.h>
#include <cstdint>

// ---------------------------------------------------------------------------
// GCN 3-layer encoder.
//   per layer: h = X @ W ;  g = dinv * h
//              agg = g; agg[dst] += g[src]  (scatter over edges)
//              out = dinv * agg + b   (+ ReLU except last layer)
// dinv = rsqrt(1 + in-degree), computed once.
// ---------------------------------------------------------------------------

#define MAX_NODES 100000
#define MAX_FEAT  128

__device__ float g_buf[MAX_NODES * MAX_FEAT];
__device__ float agg_buf[MAX_NODES * MAX_FEAT];
__device__ float act_buf[MAX_NODES * MAX_FEAT];
__device__ float dinv_buf[MAX_NODES];

// ---------------------------------------------------------------------------
__global__ void fill_kernel(float* __restrict__ p, float v, int n) {
    int i = blockIdx.x * blockDim.x + threadIdx.x;
    if (i < n) p[i] = v;
}

__global__ void deg_kernel(const int* __restrict__ dst, float* __restrict__ deg, int E) {
    int e = blockIdx.x * blockDim.x + threadIdx.x;
    if (e < E) atomicAdd(&deg[dst[e]], 1.0f);
}

__global__ void rsqrt_kernel(float* __restrict__ d, int n) {
    int i = blockIdx.x * blockDim.x + threadIdx.x;
    if (i < n) d[i] = rsqrtf(d[i]);
}

// ---------------------------------------------------------------------------
// SGEMM:  G[N, BN] = (A[N,128] @ W[128,BN]) * dinv[row]
// Writes result to BOTH G and AGG (agg initialized to self-loop term).
// BM=128, BK=32; 256 threads; microtile TM x 8.
// ---------------------------------------------------------------------------
template <int BN>
__global__ __launch_bounds__(256) void gemm_scaled_kernel(
    const float* __restrict__ A, const float* __restrict__ W,
    const float* __restrict__ dinv, float* __restrict__ G,
    float* __restrict__ AGG, int N)
{
    constexpr int BM = 128;
    constexpr int BK = 32;
    constexpr int TN = 8;
    constexpr int TM = (BM * BN) / (256 * TN);   // 8 for BN=128, 4 for BN=64
    constexpr int NCG = BN / TN;                 // col groups

    __shared__ float As[BK][BM + 4];
    __shared__ float Ws[BK][BN];

    const int tid = threadIdx.x;
    const int block_row = blockIdx.x * BM;
    const int tcol = (tid % NCG) * TN;
    const int trow = (tid / NCG) * TM;

    float acc[TM][TN];
#pragma unroll
    for (int i = 0; i < TM; i++)
#pragma unroll
        for (int j = 0; j < TN; j++) acc[i][j] = 0.f;

    for (int k0 = 0; k0 < 128; k0 += BK) {
        // A tile: BM x BK = 4096 floats = 1024 float4; 4 per thread. Stored transposed.
#pragma unroll
        for (int it = 0; it < 4; it++) {
            int f = tid + it * 256;
            int row = f >> 3;            // f / 8
            int kk = (f & 7) * 4;
            int grow = block_row + row;
            float4 v = make_float4(0.f, 0.f, 0.f, 0.f);
            if (grow < N)
                v = *(const float4*)(A + (size_t)grow * 128 + k0 + kk);
            As[kk + 0][row] = v.x;
            As[kk + 1][row] = v.y;
            As[kk + 2][row] = v.z;
            As[kk + 3][row] = v.w;
        }
        // W tile: BK x BN
        constexpr int WF4 = (BK * BN / 4) / 256;  // 4 for BN=128, 2 for BN=64
#pragma unroll
        for (int it = 0; it < WF4; it++) {
            int f = tid + it * 256;
            int krow = f / (BN / 4);
            int c = (f % (BN / 4)) * 4;
            *(float4*)(&Ws[krow][c]) = *(const float4*)(W + (size_t)(k0 + krow) * BN + c);
        }
        __syncthreads();

#pragma unroll
        for (int k = 0; k < BK; k++) {
            float a[TM], b[TN];
#pragma unroll
            for (int i = 0; i < TM; i += 4)
                *(float4*)(&a[i]) = *(const float4*)(&As[k][trow + i]);
#pragma unroll
            for (int j = 0; j < TN; j += 4)
                *(float4*)(&b[j]) = *(const float4*)(&Ws[k][tcol + j]);
#pragma unroll
            for (int i = 0; i < TM; i++)
#pragma unroll
                for (int j = 0; j < TN; j++)
                    acc[i][j] = fmaf(a[i], b[j], acc[i][j]);
        }
        __syncthreads();
    }

#pragma unroll
    for (int i = 0; i < TM; i++) {
        int grow = block_row + trow + i;
        if (grow < N) {
            float s = dinv[grow];
#pragma unroll
            for (int j = 0; j < TN; j += 4) {
                float4 v = make_float4(acc[i][j] * s, acc[i][j + 1] * s,
                                       acc[i][j + 2] * s, acc[i][j + 3] * s);
                *(float4*)(G + (size_t)grow * BN + tcol + j) = v;
                *(float4*)(AGG + (size_t)grow * BN + tcol + j) = v;
            }
        }
    }
}

// ---------------------------------------------------------------------------
// Scatter-add:  agg[dst] += g[src]   (DIM/4 lanes per edge, float4 reads)
// ---------------------------------------------------------------------------
template <int DIM>
__global__ void scatter_add_kernel(const float* __restrict__ G,
                                   const int* __restrict__ src,
                                   const int* __restrict__ dst,
                                   float* __restrict__ agg, int E)
{
    constexpr int F4 = DIM / 4;
    const int perBlock = blockDim.x / F4;
    int e = blockIdx.x * perBlock + threadIdx.x / F4;
    const int fl = (threadIdx.x % F4) * 4;
    if (e >= E) return;
    int s = src[e];
    int d = dst[e];
    float4 v = *(const float4*)(G + (size_t)s * DIM + fl);
    float* ap = agg + (size_t)d * DIM + fl;
    atomicAdd(ap + 0, v.x);
    atomicAdd(ap + 1, v.y);
    atomicAdd(ap + 2, v.z);
    atomicAdd(ap + 3, v.w);
}

// ---------------------------------------------------------------------------
// Finalize:  out = dinv*agg + b   (+ReLU)
// ---------------------------------------------------------------------------
template <int DIM, bool RELU>
__global__ void finalize_kernel(const float* __restrict__ agg,
                                const float* __restrict__ dinv,
                                const float* __restrict__ b,
                                float* __restrict__ out, int N)
{
    constexpr int F4 = DIM / 4;
    int t = blockIdx.x * blockDim.x + threadIdx.x;
    if (t >= N * F4) return;
    int node = t / F4;
    int f = (t % F4) * 4;
    float di = dinv[node];
    float4 a = *(const float4*)(agg + (size_t)node * DIM + f);
    float4 bb = *(const float4*)(b + f);
    float4 o;
    o.x = fmaf(di, a.x, bb.x);
    o.y = fmaf(di, a.y, bb.y);
    o.z = fmaf(di, a.z, bb.z);
    o.w = fmaf(di, a.w, bb.w);
    if (RELU) {
        o.x = fmaxf(o.x, 0.f);
        o.y = fmaxf(o.y, 0.f);
        o.z = fmaxf(o.z, 0.f);
        o.w = fmaxf(o.w, 0.f);
    }
    *(float4*)(out + (size_t)node * DIM + f) = o;
}

// ---------------------------------------------------------------------------
static inline int cdiv(int a, int b) { return (a + b - 1) / b; }

extern "C" void kernel_launch(void* const* d_in, const int* in_sizes, int n_in,
                              void* d_out, int out_size)
{
    const float* x  = (const float*)d_in[0];
    const int*   ei = (const int*)d_in[1];
    const float* W1 = (const float*)d_in[2];
    const float* b1 = (const float*)d_in[3];
    const float* W2 = (const float*)d_in[4];
    const float* b2 = (const float*)d_in[5];
    const float* W3 = (const float*)d_in[6];
    const float* b3 = (const float*)d_in[7];
    float* out = (float*)d_out;

    const int N = in_sizes[0] / 128;
    const int E = in_sizes[1] / 2;
    const int* src = ei;
    const int* dst = ei + E;

    float *g, *agg, *act, *dinv;
    cudaGetSymbolAddress((void**)&g, g_buf);
    cudaGetSymbolAddress((void**)&agg, agg_buf);
    cudaGetSymbolAddress((void**)&act, act_buf);
    cudaGetSymbolAddress((void**)&dinv, dinv_buf);

    // --- degrees -> dinv (once) ---
    fill_kernel<<<cdiv(N, 256), 256>>>(dinv, 1.0f, N);
    deg_kernel<<<cdiv(E, 256), 256>>>(dst, dinv, E);
    rsqrt_kernel<<<cdiv(N, 256), 256>>>(dinv, N);

    const int gemm_blocks = cdiv(N, 128);

    // ---------------- layer 1 (128 -> 128, ReLU) ----------------
    gemm_scaled_kernel<128><<<gemm_blocks, 256>>>(x, W1, dinv, g, agg, N);
    scatter_add_kernel<128><<<cdiv(E, 8), 256>>>(g, src, dst, agg, E);
    finalize_kernel<128, true><<<cdiv(N * 32, 256), 256>>>(agg, dinv, b1, act, N);

    // ---------------- layer 2 (128 -> 128, ReLU) ----------------
    gemm_scaled_kernel<128><<<gemm_blocks, 256>>>(act, W2, dinv, g, agg, N);
    scatter_add_kernel<128><<<cdiv(E, 8), 256>>>(g, src, dst, agg, E);
    finalize_kernel<128, true><<<cdiv(N * 32, 256), 256>>>(agg, dinv, b2, act, N);

    // ---------------- layer 3 (128 -> 64, no activation) ----------------
    gemm_scaled_kernel<64><<<gemm_blocks, 256>>>(act, W3, dinv, g, agg, N);
    scatter_add_kernel<64><<<cdiv(E, 16), 256>>>(g, src, dst, agg, E);
    finalize_kernel<64, false><<<cdiv(N * 16, 256), 256>>>(agg, dinv, b3, out, N);
}

// round 3
// speedup vs baseline: 3.2352x; 3.2352x over previous
#include <cuda_runtime.h>
#include <cuda_bf16.h>
#include <cstdint>

// ---------------------------------------------------------------------------
// GCN 3-layer encoder, CSR-gather formulation (no scatter atomics in hot path).
//   once:      CSR build (counts -> scan -> placement), dinv = rsqrt(1+deg)
//   per layer: g = (X @ W) * dinv          [SGEMM, fused row scale]
//              out[i] = dinv[i]*(sum_{j in N(i)} g[j] + g[i]) + b  (+ReLU)
// ---------------------------------------------------------------------------

#define MAX_NODES 100000
#define MAX_EDGES 1600000
#define SCAN_BLK  1024
#define MAX_SCAN_BLOCKS 128   // ceil(100000/1024)=98

__device__ float g_buf[MAX_NODES * 128];
__device__ float act_buf[MAX_NODES * 128];
__device__ float dinv_buf[MAX_NODES];
__device__ int   cnt_buf[MAX_NODES];
__device__ int   inc_buf[MAX_NODES];
__device__ int   bsum_buf[MAX_SCAN_BLOCKS];
__device__ int   rowptr_buf[MAX_NODES + 1];
__device__ int   cursor_buf[MAX_NODES];
__device__ int   cols_buf[MAX_EDGES];

// ---------------------------------------------------------------------------
__global__ void zero_int_kernel(int* __restrict__ p, int n) {
    int i = blockIdx.x * blockDim.x + threadIdx.x;
    if (i < n) p[i] = 0;
}

__global__ void count_kernel(const int* __restrict__ dst, int* __restrict__ cnt, int E) {
    int e = blockIdx.x * blockDim.x + threadIdx.x;
    if (e < E) atomicAdd(&cnt[dst[e]], 1);
}

// per-block inclusive scan; emits per-block totals
__global__ void scan_block_kernel(const int* __restrict__ in, int* __restrict__ out,
                                  int* __restrict__ bsums, int n) {
    __shared__ int sh[SCAN_BLK];
    int i = blockIdx.x * SCAN_BLK + threadIdx.x;
    sh[threadIdx.x] = (i < n) ? in[i] : 0;
    __syncthreads();
#pragma unroll
    for (int off = 1; off < SCAN_BLK; off <<= 1) {
        int t = (threadIdx.x >= off) ? sh[threadIdx.x - off] : 0;
        __syncthreads();
        sh[threadIdx.x] += t;
        __syncthreads();
    }
    if (i < n) out[i] = sh[threadIdx.x];
    if (threadIdx.x == SCAN_BLK - 1) bsums[blockIdx.x] = sh[threadIdx.x];
}

// single-block inclusive scan of block sums (nb <= 128)
__global__ void scan_sums_kernel(int* __restrict__ bsums, int nb) {
    __shared__ int sh[MAX_SCAN_BLOCKS];
    int v = (threadIdx.x < nb) ? bsums[threadIdx.x] : 0;
    sh[threadIdx.x] = v;
    __syncthreads();
#pragma unroll
    for (int off = 1; off < MAX_SCAN_BLOCKS; off <<= 1) {
        int t = (threadIdx.x >= off) ? sh[threadIdx.x - off] : 0;
        __syncthreads();
        sh[threadIdx.x] += t;
        __syncthreads();
    }
    if (threadIdx.x < nb) bsums[threadIdx.x] = sh[threadIdx.x];
}

// rowptr[i+1] = global inclusive; cursor[i] = exclusive; dinv[i] = rsqrt(1+cnt)
__global__ void finalize_scan_kernel(const int* __restrict__ inc, const int* __restrict__ bsums,
                                     const int* __restrict__ cnt, int* __restrict__ rowptr,
                                     int* __restrict__ cursor, float* __restrict__ dinv, int n) {
    int i = blockIdx.x * SCAN_BLK + threadIdx.x;
    if (i >= n) return;
    int add = (blockIdx.x > 0) ? bsums[blockIdx.x - 1] : 0;
    int v = inc[i] + add;
    rowptr[i + 1] = v;
    cursor[i] = v - cnt[i];
    dinv[i] = rsqrtf(1.0f + (float)cnt[i]);
    if (i == 0) rowptr[0] = 0;
}

__global__ void fill_cols_kernel(const int* __restrict__ src, const int* __restrict__ dst,
                                 int* __restrict__ cursor, int* __restrict__ cols, int E) {
    int e = blockIdx.x * blockDim.x + threadIdx.x;
    if (e < E) {
        int pos = atomicAdd(&cursor[dst[e]], 1);
        cols[pos] = src[e];
    }
}

// ---------------------------------------------------------------------------
// SGEMM:  G[N, BN] = (A[N,128] @ W[128,BN]) * dinv[row]
// ---------------------------------------------------------------------------
template <int BN>
__global__ __launch_bounds__(256) void gemm_scaled_kernel(
    const float* __restrict__ A, const float* __restrict__ W,
    const float* __restrict__ dinv, float* __restrict__ G, int N)
{
    constexpr int BM = 128;
    constexpr int BK = 32;
    constexpr int TN = 8;
    constexpr int TM = (BM * BN) / (256 * TN);
    constexpr int NCG = BN / TN;

    __shared__ float As[BK][BM + 4];
    __shared__ float Ws[BK][BN];

    const int tid = threadIdx.x;
    const int block_row = blockIdx.x * BM;
    const int tcol = (tid % NCG) * TN;
    const int trow = (tid / NCG) * TM;

    float acc[TM][TN];
#pragma unroll
    for (int i = 0; i < TM; i++)
#pragma unroll
        for (int j = 0; j < TN; j++) acc[i][j] = 0.f;

    for (int k0 = 0; k0 < 128; k0 += BK) {
#pragma unroll
        for (int it = 0; it < 4; it++) {
            int f = tid + it * 256;
            int row = f >> 3;
            int kk = (f & 7) * 4;
            int grow = block_row + row;
            float4 v = make_float4(0.f, 0.f, 0.f, 0.f);
            if (grow < N)
                v = *(const float4*)(A + (size_t)grow * 128 + k0 + kk);
            As[kk + 0][row] = v.x;
            As[kk + 1][row] = v.y;
            As[kk + 2][row] = v.z;
            As[kk + 3][row] = v.w;
        }
        constexpr int WF4 = (BK * BN / 4) / 256;
#pragma unroll
        for (int it = 0; it < WF4; it++) {
            int f = tid + it * 256;
            int krow = f / (BN / 4);
            int c = (f % (BN / 4)) * 4;
            *(float4*)(&Ws[krow][c]) = *(const float4*)(W + (size_t)(k0 + krow) * BN + c);
        }
        __syncthreads();

#pragma unroll
        for (int k = 0; k < BK; k++) {
            float a[TM], b[TN];
#pragma unroll
            for (int i = 0; i < TM; i += 4)
                *(float4*)(&a[i]) = *(const float4*)(&As[k][trow + i]);
#pragma unroll
            for (int j = 0; j < TN; j += 4)
                *(float4*)(&b[j]) = *(const float4*)(&Ws[k][tcol + j]);
#pragma unroll
            for (int i = 0; i < TM; i++)
#pragma unroll
                for (int j = 0; j < TN; j++)
                    acc[i][j] = fmaf(a[i], b[j], acc[i][j]);
        }
        __syncthreads();
    }

#pragma unroll
    for (int i = 0; i < TM; i++) {
        int grow = block_row + trow + i;
        if (grow < N) {
            float s = dinv[grow];
#pragma unroll
            for (int j = 0; j < TN; j += 4) {
                float4 v = make_float4(acc[i][j] * s, acc[i][j + 1] * s,
                                       acc[i][j + 2] * s, acc[i][j + 3] * s);
                *(float4*)(G + (size_t)grow * BN + tcol + j) = v;
            }
        }
    }
}

// ---------------------------------------------------------------------------
// Fused gather + finalize, DIM=128: warp per node, float4 per lane.
// ---------------------------------------------------------------------------
template <bool RELU>
__global__ __launch_bounds__(256) void gather128_kernel(
    const float* __restrict__ G, const int* __restrict__ rowptr,
    const int* __restrict__ cols, const float* __restrict__ dinv,
    const float* __restrict__ b, float* __restrict__ out, int N)
{
    int warp = (blockIdx.x * blockDim.x + threadIdx.x) >> 5;
    int lane = threadIdx.x & 31;
    if (warp >= N) return;
    const int fl = lane * 4;
    int beg = rowptr[warp];
    int end = rowptr[warp + 1];

    // self-loop term
    float4 acc = *(const float4*)(G + (size_t)warp * 128 + fl);

    int e = beg;
    for (; e + 4 <= end; e += 4) {
        int c0 = cols[e + 0];
        int c1 = cols[e + 1];
        int c2 = cols[e + 2];
        int c3 = cols[e + 3];
        float4 v0 = *(const float4*)(G + (size_t)c0 * 128 + fl);
        float4 v1 = *(const float4*)(G + (size_t)c1 * 128 + fl);
        float4 v2 = *(const float4*)(G + (size_t)c2 * 128 + fl);
        float4 v3 = *(const float4*)(G + (size_t)c3 * 128 + fl);
        acc.x += v0.x + v1.x + v2.x + v3.x;
        acc.y += v0.y + v1.y + v2.y + v3.y;
        acc.z += v0.z + v1.z + v2.z + v3.z;
        acc.w += v0.w + v1.w + v2.w + v3.w;
    }
    for (; e < end; e++) {
        int c = cols[e];
        float4 v = *(const float4*)(G + (size_t)c * 128 + fl);
        acc.x += v.x; acc.y += v.y; acc.z += v.z; acc.w += v.w;
    }

    float di = dinv[warp];
    float4 bb = *(const float4*)(b + fl);
    float4 o;
    o.x = fmaf(di, acc.x, bb.x);
    o.y = fmaf(di, acc.y, bb.y);
    o.z = fmaf(di, acc.z, bb.z);
    o.w = fmaf(di, acc.w, bb.w);
    if (RELU) {
        o.x = fmaxf(o.x, 0.f);
        o.y = fmaxf(o.y, 0.f);
        o.z = fmaxf(o.z, 0.f);
        o.w = fmaxf(o.w, 0.f);
    }
    *(float4*)(out + (size_t)warp * 128 + fl) = o;
}

// DIM=64 variant: warp per node, float2 per lane.
template <bool RELU>
__global__ __launch_bounds__(256) void gather64_kernel(
    const float* __restrict__ G, const int* __restrict__ rowptr,
    const int* __restrict__ cols, const float* __restrict__ dinv,
    const float* __restrict__ b, float* __restrict__ out, int N)
{
    int warp = (blockIdx.x * blockDim.x + threadIdx.x) >> 5;
    int lane = threadIdx.x & 31;
    if (warp >= N) return;
    const int fl = lane * 2;
    int beg = rowptr[warp];
    int end = rowptr[warp + 1];

    float2 acc = *(const float2*)(G + (size_t)warp * 64 + fl);

    int e = beg;
    for (; e + 4 <= end; e += 4) {
        int c0 = cols[e + 0];
        int c1 = cols[e + 1];
        int c2 = cols[e + 2];
        int c3 = cols[e + 3];
        float2 v0 = *(const float2*)(G + (size_t)c0 * 64 + fl);
        float2 v1 = *(const float2*)(G + (size_t)c1 * 64 + fl);
        float2 v2 = *(const float2*)(G + (size_t)c2 * 64 + fl);
        float2 v3 = *(const float2*)(G + (size_t)c3 * 64 + fl);
        acc.x += v0.x + v1.x + v2.x + v3.x;
        acc.y += v0.y + v1.y + v2.y + v3.y;
    }
    for (; e < end; e++) {
        int c = cols[e];
        float2 v = *(const float2*)(G + (size_t)c * 64 + fl);
        acc.x += v.x; acc.y += v.y;
    }

    float di = dinv[warp];
    float2 bb = *(const float2*)(b + fl);
    float2 o;
    o.x = fmaf(di, acc.x, bb.x);
    o.y = fmaf(di, acc.y, bb.y);
    if (RELU) {
        o.x = fmaxf(o.x, 0.f);
        o.y = fmaxf(o.y, 0.f);
    }
    *(float2*)(out + (size_t)warp * 64 + fl) = o;
}

// ---------------------------------------------------------------------------
static inline int cdiv(int a, int b) { return (a + b - 1) / b; }

extern "C" void kernel_launch(void* const* d_in, const int* in_sizes, int n_in,
                              void* d_out, int out_size)
{
    const float* x  = (const float*)d_in[0];
    const int*   ei = (const int*)d_in[1];
    const float* W1 = (const float*)d_in[2];
    const float* b1 = (const float*)d_in[3];
    const float* W2 = (const float*)d_in[4];
    const float* b2 = (const float*)d_in[5];
    const float* W3 = (const float*)d_in[6];
    const float* b3 = (const float*)d_in[7];
    float* out = (float*)d_out;

    const int N = in_sizes[0] / 128;
    const int E = in_sizes[1] / 2;
    const int* src = ei;
    const int* dst = ei + E;

    float *g, *act, *dinv;
    int *cnt, *inc, *bsum, *rowptr, *cursor, *cols;
    cudaGetSymbolAddress((void**)&g, g_buf);
    cudaGetSymbolAddress((void**)&act, act_buf);
    cudaGetSymbolAddress((void**)&dinv, dinv_buf);
    cudaGetSymbolAddress((void**)&cnt, cnt_buf);
    cudaGetSymbolAddress((void**)&inc, inc_buf);
    cudaGetSymbolAddress((void**)&bsum, bsum_buf);
    cudaGetSymbolAddress((void**)&rowptr, rowptr_buf);
    cudaGetSymbolAddress((void**)&cursor, cursor_buf);
    cudaGetSymbolAddress((void**)&cols, cols_buf);

    // ---------------- CSR build + dinv (once per launch) ----------------
    const int nb = cdiv(N, SCAN_BLK);
    zero_int_kernel<<<cdiv(N, 256), 256>>>(cnt, N);
    count_kernel<<<cdiv(E, 256), 256>>>(dst, cnt, E);
    scan_block_kernel<<<nb, SCAN_BLK>>>(cnt, inc, bsum, N);
    scan_sums_kernel<<<1, MAX_SCAN_BLOCKS>>>(bsum, nb);
    finalize_scan_kernel<<<nb, SCAN_BLK>>>(inc, bsum, cnt, rowptr, cursor, dinv, N);
    fill_cols_kernel<<<cdiv(E, 256), 256>>>(src, dst, cursor, cols, E);

    const int gemm_blocks = cdiv(N, 128);
    const int gather_blocks = cdiv(N * 32, 256);

    // ---------------- layer 1 (128 -> 128, ReLU) ----------------
    gemm_scaled_kernel<128><<<gemm_blocks, 256>>>(x, W1, dinv, g, N);
    gather128_kernel<true><<<gather_blocks, 256>>>(g, rowptr, cols, dinv, b1, act, N);

    // ---------------- layer 2 (128 -> 128, ReLU) ----------------
    gemm_scaled_kernel<128><<<gemm_blocks, 256>>>(act, W2, dinv, g, N);
    gather128_kernel<true><<<gather_blocks, 256>>>(g, rowptr, cols, dinv, b2, act, N);

    // ---------------- layer 3 (128 -> 64, no activation) ----------------
    gemm_scaled_kernel<64><<<gemm_blocks, 256>>>(act, W3, dinv, g, N);
    gather64_kernel<false><<<gather_blocks, 256>>>(g, rowptr, cols, dinv, b3, out, N);
}

// round 5
// speedup vs baseline: 3.7353x; 1.1546x over previous
#include <cuda_runtime.h>
#include <cuda_bf16.h>
#include <cstdint>

// ---------------------------------------------------------------------------
// GCN 3-layer encoder. CSR gather + mma.sync (bf16 2-term split) GEMM.
//   g = (X @ W) * dinv   via  Ah*Wh + Al*Wh + Ah*Wl  (f32 accum)
//   out[i] = dinv[i]*(sum_{j in N(i)} g[j] + g[i]) + b  (+ReLU)
// ---------------------------------------------------------------------------

#define MAX_NODES 100000
#define MAX_EDGES 1600000
#define SCAN_BLK  1024
#define MAX_SCAN_BLOCKS 128

__device__ float         g_buf[MAX_NODES * 128];
__device__ __nv_bfloat16 ah_buf[MAX_NODES * 128];
__device__ __nv_bfloat16 al_buf[MAX_NODES * 128];
__device__ __nv_bfloat16 wh_buf[3 * 128 * 128];   // transposed [n][k]
__device__ __nv_bfloat16 wl_buf[3 * 128 * 128];
__device__ float dinv_buf[MAX_NODES];
__device__ int   cnt_buf[MAX_NODES];
__device__ int   inc_buf[MAX_NODES];
__device__ int   bsum_buf[MAX_SCAN_BLOCKS];
__device__ int   rowptr_buf[MAX_NODES + 1];
__device__ int   cursor_buf[MAX_NODES];
__device__ int   cols_buf[MAX_EDGES];

// ---------------------------------------------------------------------------
// CSR build helpers
// ---------------------------------------------------------------------------
__global__ void zero_int_kernel(int* __restrict__ p, int n) {
    int i = blockIdx.x * blockDim.x + threadIdx.x;
    if (i < n) p[i] = 0;
}
__global__ void count_kernel(const int* __restrict__ dst, int* __restrict__ cnt, int E) {
    int e = blockIdx.x * blockDim.x + threadIdx.x;
    if (e < E) atomicAdd(&cnt[dst[e]], 1);
}
__global__ void scan_block_kernel(const int* __restrict__ in, int* __restrict__ out,
                                  int* __restrict__ bsums, int n) {
    __shared__ int sh[SCAN_BLK];
    int i = blockIdx.x * SCAN_BLK + threadIdx.x;
    sh[threadIdx.x] = (i < n) ? in[i] : 0;
    __syncthreads();
#pragma unroll
    for (int off = 1; off < SCAN_BLK; off <<= 1) {
        int t = (threadIdx.x >= off) ? sh[threadIdx.x - off] : 0;
        __syncthreads();
        sh[threadIdx.x] += t;
        __syncthreads();
    }
    if (i < n) out[i] = sh[threadIdx.x];
    if (threadIdx.x == SCAN_BLK - 1) bsums[blockIdx.x] = sh[threadIdx.x];
}
__global__ void scan_sums_kernel(int* __restrict__ bsums, int nb) {
    __shared__ int sh[MAX_SCAN_BLOCKS];
    int v = (threadIdx.x < nb) ? bsums[threadIdx.x] : 0;
    sh[threadIdx.x] = v;
    __syncthreads();
#pragma unroll
    for (int off = 1; off < MAX_SCAN_BLOCKS; off <<= 1) {
        int t = (threadIdx.x >= off) ? sh[threadIdx.x - off] : 0;
        __syncthreads();
        sh[threadIdx.x] += t;
        __syncthreads();
    }
    if (threadIdx.x < nb) bsums[threadIdx.x] = sh[threadIdx.x];
}
__global__ void finalize_scan_kernel(const int* __restrict__ inc, const int* __restrict__ bsums,
                                     const int* __restrict__ cnt, int* __restrict__ rowptr,
                                     int* __restrict__ cursor, float* __restrict__ dinv, int n) {
    int i = blockIdx.x * SCAN_BLK + threadIdx.x;
    if (i >= n) return;
    int add = (blockIdx.x > 0) ? bsums[blockIdx.x - 1] : 0;
    int v = inc[i] + add;
    rowptr[i + 1] = v;
    cursor[i] = v - cnt[i];
    dinv[i] = rsqrtf(1.0f + (float)cnt[i]);
    if (i == 0) rowptr[0] = 0;
}
__global__ void fill_cols_kernel(const int* __restrict__ src, const int* __restrict__ dst,
                                 int* __restrict__ cursor, int* __restrict__ cols, int E) {
    int e = blockIdx.x * blockDim.x + threadIdx.x;
    if (e < E) {
        int pos = atomicAdd(&cursor[dst[e]], 1);
        cols[pos] = src[e];
    }
}

// ---------------------------------------------------------------------------
// bf16 2-term split helpers
// ---------------------------------------------------------------------------
__device__ __forceinline__ void split2(float v, __nv_bfloat16& h, __nv_bfloat16& l) {
    h = __float2bfloat16(v);
    l = __float2bfloat16(v - __bfloat162float(h));
}

__global__ void split_kernel(const float* __restrict__ x,
                             __nv_bfloat16* __restrict__ hi,
                             __nv_bfloat16* __restrict__ lo, int n4) {
    int i = blockIdx.x * blockDim.x + threadIdx.x;
    if (i >= n4) return;
    float4 v = *(const float4*)(x + (size_t)i * 4);
    __nv_bfloat16 h0, l0, h1, l1, h2, l2, h3, l3;
    split2(v.x, h0, l0); split2(v.y, h1, l1); split2(v.z, h2, l2); split2(v.w, h3, l3);
    __nv_bfloat162 hh0 = {h0, h1}, hh1 = {h2, h3};
    __nv_bfloat162 ll0 = {l0, l1}, ll1 = {l2, l3};
    *(uint2*)(hi + (size_t)i * 4) = make_uint2(*(uint32_t*)&hh0, *(uint32_t*)&hh1);
    *(uint2*)(lo + (size_t)i * 4) = make_uint2(*(uint32_t*)&ll0, *(uint32_t*)&ll1);
}

// W [128(k), BN(n)] -> Wt hi/lo [BN][128] (n rows, k contiguous)
__global__ void wsplit_kernel(const float* __restrict__ W,
                              __nv_bfloat16* __restrict__ hi,
                              __nv_bfloat16* __restrict__ lo, int BN) {
    int i = blockIdx.x * blockDim.x + threadIdx.x;
    if (i >= BN * 128) return;
    int nrow = i >> 7;
    int k = i & 127;
    float v = W[(size_t)k * BN + nrow];
    __nv_bfloat16 h, l;
    split2(v, h, l);
    hi[i] = h; lo[i] = l;
}

// ---------------------------------------------------------------------------
// mma.sync bf16-split GEMM: G[N, BN] = (A @ W) * dinv[row]
// One CTA = 128 x BN x 128. 256 threads (8 warps: 4 along M, 2 along N).
// SMEM rows padded to 136 bf16 for conflict-free fragment LDS.
// ---------------------------------------------------------------------------
#define SMPITCH 136

__device__ __forceinline__ void mma16816(float* c, const uint32_t* a, const uint32_t* b) {
    asm volatile(
        "mma.sync.aligned.m16n8k16.row.col.f32.bf16.bf16.f32 "
        "{%0,%1,%2,%3}, {%4,%5,%6,%7}, {%8,%9}, {%0,%1,%2,%3};"
        : "+f"(c[0]), "+f"(c[1]), "+f"(c[2]), "+f"(c[3])
        : "r"(a[0]), "r"(a[1]), "r"(a[2]), "r"(a[3]), "r"(b[0]), "r"(b[1]));
}

template <int BN>
__global__ __launch_bounds__(256, 1) void gemm_mma_kernel(
    const __nv_bfloat16* __restrict__ Ah, const __nv_bfloat16* __restrict__ Al,
    const __nv_bfloat16* __restrict__ Wh, const __nv_bfloat16* __restrict__ Wl,
    const float* __restrict__ dinv, float* __restrict__ G, int N)
{
    constexpr int NT = BN / 16;          // n-tiles per warp (8 or 4)
    extern __shared__ __nv_bfloat16 sm[];
    __nv_bfloat16* sAh = sm;
    __nv_bfloat16* sAl = sAh + 128 * SMPITCH;
    __nv_bfloat16* sWh = sAl + 128 * SMPITCH;
    __nv_bfloat16* sWl = sWh + BN * SMPITCH;

    const int tid = threadIdx.x;
    const int wid = tid >> 5;
    const int lane = tid & 31;
    const int warp_m = wid & 3;          // 0..3 -> 32-row slab
    const int warp_n = wid >> 2;         // 0..1 -> BN/2 col slab
    const int g = lane >> 2;             // group 0..7
    const int tg = lane & 3;             // thread-in-group 0..3
    const int block_row = blockIdx.x * 128;

    // ---- load A tiles (hi & lo), 8 bf16 per uint4 ----
    for (int i = tid; i < 128 * 16; i += 256) {
        int row = i >> 4, c = i & 15;
        int grow = block_row + row;
        uint4 vh = make_uint4(0, 0, 0, 0), vl = make_uint4(0, 0, 0, 0);
        if (grow < N) {
            vh = *(const uint4*)(Ah + (size_t)grow * 128 + c * 8);
            vl = *(const uint4*)(Al + (size_t)grow * 128 + c * 8);
        }
        *(uint4*)(sAh + row * SMPITCH + c * 8) = vh;
        *(uint4*)(sAl + row * SMPITCH + c * 8) = vl;
    }
    // ---- load W tiles [BN][128] ----
    for (int i = tid; i < BN * 16; i += 256) {
        int row = i >> 4, c = i & 15;
        *(uint4*)(sWh + row * SMPITCH + c * 8) = *(const uint4*)(Wh + (size_t)row * 128 + c * 8);
        *(uint4*)(sWl + row * SMPITCH + c * 8) = *(const uint4*)(Wl + (size_t)row * 128 + c * 8);
    }
    __syncthreads();

    float acc[2][NT][4];
#pragma unroll
    for (int i = 0; i < 2; i++)
#pragma unroll
        for (int j = 0; j < NT; j++)
#pragma unroll
            for (int q = 0; q < 4; q++) acc[i][j][q] = 0.f;

#pragma unroll
    for (int ks = 0; ks < 8; ks++) {
        const int kb = ks * 16;
        uint32_t ah[2][4], al[2][4];
#pragma unroll
        for (int i = 0; i < 2; i++) {
            int rb = warp_m * 32 + i * 16;
            const __nv_bfloat16* ph = sAh + (rb + g) * SMPITCH + kb;
            const __nv_bfloat16* ph8 = sAh + (rb + g + 8) * SMPITCH + kb;
            const __nv_bfloat16* pl = sAl + (rb + g) * SMPITCH + kb;
            const __nv_bfloat16* pl8 = sAl + (rb + g + 8) * SMPITCH + kb;
            ah[i][0] = *(const uint32_t*)(ph + tg * 2);
            ah[i][1] = *(const uint32_t*)(ph8 + tg * 2);
            ah[i][2] = *(const uint32_t*)(ph + 8 + tg * 2);
            ah[i][3] = *(const uint32_t*)(ph8 + 8 + tg * 2);
            al[i][0] = *(const uint32_t*)(pl + tg * 2);
            al[i][1] = *(const uint32_t*)(pl8 + tg * 2);
            al[i][2] = *(const uint32_t*)(pl + 8 + tg * 2);
            al[i][3] = *(const uint32_t*)(pl8 + 8 + tg * 2);
        }
#pragma unroll
        for (int j = 0; j < NT; j++) {
            int nb = warp_n * (BN / 2) + j * 8;
            const __nv_bfloat16* pwh = sWh + (nb + g) * SMPITCH + kb;
            const __nv_bfloat16* pwl = sWl + (nb + g) * SMPITCH + kb;
            uint32_t bh[2], bl[2];
            bh[0] = *(const uint32_t*)(pwh + tg * 2);
            bh[1] = *(const uint32_t*)(pwh + 8 + tg * 2);
            bl[0] = *(const uint32_t*)(pwl + tg * 2);
            bl[1] = *(const uint32_t*)(pwl + 8 + tg * 2);
#pragma unroll
            for (int i = 0; i < 2; i++) {
                mma16816(acc[i][j], ah[i], bh);
                mma16816(acc[i][j], al[i], bh);
                mma16816(acc[i][j], ah[i], bl);
            }
        }
    }

    // ---- epilogue: scale by dinv[row], store fp32 ----
#pragma unroll
    for (int i = 0; i < 2; i++) {
        int r0 = block_row + warp_m * 32 + i * 16 + g;
        int r1 = r0 + 8;
        float s0 = (r0 < N) ? dinv[r0] : 0.f;
        float s1 = (r1 < N) ? dinv[r1] : 0.f;
#pragma unroll
        for (int j = 0; j < NT; j++) {
            int c = warp_n * (BN / 2) + j * 8 + tg * 2;
            if (r0 < N) {
                float2 v = make_float2(acc[i][j][0] * s0, acc[i][j][1] * s0);
                *(float2*)(G + (size_t)r0 * BN + c) = v;
            }
            if (r1 < N) {
                float2 v = make_float2(acc[i][j][2] * s1, acc[i][j][3] * s1);
                *(float2*)(G + (size_t)r1 * BN + c) = v;
            }
        }
    }
}

// ---------------------------------------------------------------------------
// Fused gather + finalize (DIM=128): warp per node, writes bf16 hi/lo.
// ---------------------------------------------------------------------------
__global__ __launch_bounds__(256) void gather128_split_kernel(
    const float* __restrict__ G, const int* __restrict__ rowptr,
    const int* __restrict__ cols, const float* __restrict__ dinv,
    const float* __restrict__ b,
    __nv_bfloat16* __restrict__ outh, __nv_bfloat16* __restrict__ outl, int N)
{
    int warp = (blockIdx.x * blockDim.x + threadIdx.x) >> 5;
    int lane = threadIdx.x & 31;
    if (warp >= N) return;
    const int fl = lane * 4;
    int beg = rowptr[warp];
    int end = rowptr[warp + 1];

    float4 acc = *(const float4*)(G + (size_t)warp * 128 + fl);  // self-loop

    int e = beg;
    for (; e + 4 <= end; e += 4) {
        int c0 = cols[e + 0], c1 = cols[e + 1], c2 = cols[e + 2], c3 = cols[e + 3];
        float4 v0 = *(const float4*)(G + (size_t)c0 * 128 + fl);
        float4 v1 = *(const float4*)(G + (size_t)c1 * 128 + fl);
        float4 v2 = *(const float4*)(G + (size_t)c2 * 128 + fl);
        float4 v3 = *(const float4*)(G + (size_t)c3 * 128 + fl);
        acc.x += v0.x + v1.x + v2.x + v3.x;
        acc.y += v0.y + v1.y + v2.y + v3.y;
        acc.z += v0.z + v1.z + v2.z + v3.z;
        acc.w += v0.w + v1.w + v2.w + v3.w;
    }
    for (; e < end; e++) {
        int c = cols[e];
        float4 v = *(const float4*)(G + (size_t)c * 128 + fl);
        acc.x += v.x; acc.y += v.y; acc.z += v.z; acc.w += v.w;
    }

    float di = dinv[warp];
    float4 bb = *(const float4*)(b + fl);
    float4 o;
    o.x = fmaxf(fmaf(di, acc.x, bb.x), 0.f);
    o.y = fmaxf(fmaf(di, acc.y, bb.y), 0.f);
    o.z = fmaxf(fmaf(di, acc.z, bb.z), 0.f);
    o.w = fmaxf(fmaf(di, acc.w, bb.w), 0.f);

    __nv_bfloat16 h0, l0, h1, l1, h2, l2, h3, l3;
    split2(o.x, h0, l0); split2(o.y, h1, l1); split2(o.z, h2, l2); split2(o.w, h3, l3);
    __nv_bfloat162 hh0 = {h0, h1}, hh1 = {h2, h3};
    __nv_bfloat162 ll0 = {l0, l1}, ll1 = {l2, l3};
    *(uint2*)(outh + (size_t)warp * 128 + fl) = make_uint2(*(uint32_t*)&hh0, *(uint32_t*)&hh1);
    *(uint2*)(outl + (size_t)warp * 128 + fl) = make_uint2(*(uint32_t*)&ll0, *(uint32_t*)&ll1);
}

// DIM=64, final layer: fp32 output, no activation.
__global__ __launch_bounds__(256) void gather64_kernel(
    const float* __restrict__ G, const int* __restrict__ rowptr,
    const int* __restrict__ cols, const float* __restrict__ dinv,
    const float* __restrict__ b, float* __restrict__ out, int N)
{
    int warp = (blockIdx.x * blockDim.x + threadIdx.x) >> 5;
    int lane = threadIdx.x & 31;
    if (warp >= N) return;
    const int fl = lane * 2;
    int beg = rowptr[warp];
    int end = rowptr[warp + 1];

    float2 acc = *(const float2*)(G + (size_t)warp * 64 + fl);

    int e = beg;
    for (; e + 4 <= end; e += 4) {
        int c0 = cols[e + 0], c1 = cols[e + 1], c2 = cols[e + 2], c3 = cols[e + 3];
        float2 v0 = *(const float2*)(G + (size_t)c0 * 64 + fl);
        float2 v1 = *(const float2*)(G + (size_t)c1 * 64 + fl);
        float2 v2 = *(const float2*)(G + (size_t)c2 * 64 + fl);
        float2 v3 = *(const float2*)(G + (size_t)c3 * 64 + fl);
        acc.x += v0.x + v1.x + v2.x + v3.x;
        acc.y += v0.y + v1.y + v2.y + v3.y;
    }
    for (; e < end; e++) {
        int c = cols[e];
        float2 v = *(const float2*)(G + (size_t)c * 64 + fl);
        acc.x += v.x; acc.y += v.y;
    }

    float di = dinv[warp];
    float2 bb = *(const float2*)(b + fl);
    float2 o;
    o.x = fmaf(di, acc.x, bb.x);
    o.y = fmaf(di, acc.y, bb.y);
    *(float2*)(out + (size_t)warp * 64 + fl) = o;
}

// ---------------------------------------------------------------------------
static inline int cdiv(int a, int b) { return (a + b - 1) / b; }

extern "C" void kernel_launch(void* const* d_in, const int* in_sizes, int n_in,
                              void* d_out, int out_size)
{
    const float* x  = (const float*)d_in[0];
    const int*   ei = (const int*)d_in[1];
    const float* W1 = (const float*)d_in[2];
    const float* b1 = (const float*)d_in[3];
    const float* W2 = (const float*)d_in[4];
    const float* b2 = (const float*)d_in[5];
    const float* W3 = (const float*)d_in[6];
    const float* b3 = (const float*)d_in[7];
    float* out = (float*)d_out;

    const int N = in_sizes[0] / 128;
    const int E = in_sizes[1] / 2;
    const int* src = ei;
    const int* dst = ei + E;

    float *g, *dinv;
    __nv_bfloat16 *ah, *al, *wh, *wl;
    int *cnt, *inc, *bsum, *rowptr, *cursor, *cols;
    cudaGetSymbolAddress((void**)&g, g_buf);
    cudaGetSymbolAddress((void**)&ah, ah_buf);
    cudaGetSymbolAddress((void**)&al, al_buf);
    cudaGetSymbolAddress((void**)&wh, wh_buf);
    cudaGetSymbolAddress((void**)&wl, wl_buf);
    cudaGetSymbolAddress((void**)&dinv, dinv_buf);
    cudaGetSymbolAddress((void**)&cnt, cnt_buf);
    cudaGetSymbolAddress((void**)&inc, inc_buf);
    cudaGetSymbolAddress((void**)&bsum, bsum_buf);
    cudaGetSymbolAddress((void**)&rowptr, rowptr_buf);
    cudaGetSymbolAddress((void**)&cursor, cursor_buf);
    cudaGetSymbolAddress((void**)&cols, cols_buf);

    constexpr int SMEM_128 = (2 * 128 + 2 * 128) * SMPITCH * 2;  // 139264
    constexpr int SMEM_64  = (2 * 128 + 2 * 64) * SMPITCH * 2;   // 104448
    cudaFuncSetAttribute(gemm_mma_kernel<128>, cudaFuncAttributeMaxDynamicSharedMemorySize, SMEM_128);
    cudaFuncSetAttribute(gemm_mma_kernel<64>,  cudaFuncAttributeMaxDynamicSharedMemorySize, SMEM_64);

    // ---------------- CSR build + dinv ----------------
    const int nb = cdiv(N, SCAN_BLK);
    zero_int_kernel<<<cdiv(N, 256), 256>>>(cnt, N);
    count_kernel<<<cdiv(E, 256), 256>>>(dst, cnt, E);
    scan_block_kernel<<<nb, SCAN_BLK>>>(cnt, inc, bsum, N);
    scan_sums_kernel<<<1, MAX_SCAN_BLOCKS>>>(bsum, nb);
    finalize_scan_kernel<<<nb, SCAN_BLK>>>(inc, bsum, cnt, rowptr, cursor, dinv, N);
    fill_cols_kernel<<<cdiv(E, 256), 256>>>(src, dst, cursor, cols, E);

    // ---------------- input / weight splits ----------------
    split_kernel<<<cdiv(N * 32, 256), 256>>>(x, ah, al, N * 32);
    wsplit_kernel<<<cdiv(128 * 128, 256), 256>>>(W1, wh + 0 * 16384, wl + 0 * 16384, 128);
    wsplit_kernel<<<cdiv(128 * 128, 256), 256>>>(W2, wh + 1 * 16384, wl + 1 * 16384, 128);
    wsplit_kernel<<<cdiv(64 * 128, 256), 256>>>(W3, wh + 2 * 16384, wl + 2 * 16384, 64);

    const int gemm_blocks = cdiv(N, 128);
    const int gather_blocks = cdiv(N * 32, 256);

    // ---------------- layer 1 (128 -> 128, ReLU) ----------------
    gemm_mma_kernel<128><<<gemm_blocks, 256, SMEM_128>>>(ah, al, wh, wl, dinv, g, N);
    gather128_split_kernel<<<gather_blocks, 256>>>(g, rowptr, cols, dinv, b1, ah, al, N);

    // ---------------- layer 2 (128 -> 128, ReLU) ----------------
    gemm_mma_kernel<128><<<gemm_blocks, 256, SMEM_128>>>(ah, al, wh + 16384, wl + 16384, dinv, g, N);
    gather128_split_kernel<<<gather_blocks, 256>>>(g, rowptr, cols, dinv, b2, ah, al, N);

    // ---------------- layer 3 (128 -> 64, no activation) ----------------
    gemm_mma_kernel<64><<<gemm_blocks, 256, SMEM_64>>>(ah, al, wh + 2 * 16384, wl + 2 * 16384, dinv, g, N);
    gather64_kernel<<<gather_blocks, 256>>>(g, rowptr, cols, dinv, b3, out, N);
}

// round 7
// speedup vs baseline: 3.9561x; 1.0591x over previous
#include <cuda_runtime.h>
#include <cuda_bf16.h>
#include <cstdint>

// ---------------------------------------------------------------------------
// GCN 3-layer encoder. CSR gather + mma.sync (bf16 2-term split) GEMM.
//   g = (X @ W) * dinv   via  Ah*Wh + Al*Wh + Ah*Wl  (f32 accum)
//   out[i] = dinv[i]*(sum_{j in N(i)} g[j] + g[i]) + b  (+ReLU)
// ---------------------------------------------------------------------------

#define MAX_NODES 100000
#define MAX_EDGES 1600000
#define SCAN_BLK  1024
#define MAX_SCAN_BLOCKS 128

__device__ float         g_buf[MAX_NODES * 128];
__device__ __nv_bfloat16 ah_buf[MAX_NODES * 128];
__device__ __nv_bfloat16 al_buf[MAX_NODES * 128];
__device__ __nv_bfloat16 wh_buf[3 * 128 * 128];   // transposed [n][k]
__device__ __nv_bfloat16 wl_buf[3 * 128 * 128];
__device__ float dinv_buf[MAX_NODES];
__device__ int   cnt_buf[MAX_NODES];
__device__ int   inc_buf[MAX_NODES];
__device__ int   bsum_buf[MAX_SCAN_BLOCKS];
__device__ int   rowptr_buf[MAX_NODES + 1];
__device__ int   cursor_buf[MAX_NODES];
__device__ int   cols_buf[MAX_EDGES];

// ---------------------------------------------------------------------------
// CSR build helpers
// ---------------------------------------------------------------------------
__global__ void zero_int_kernel(int* __restrict__ p, int n) {
    int i = blockIdx.x * blockDim.x + threadIdx.x;
    if (i < n) p[i] = 0;
}
__global__ void count_kernel(const int* __restrict__ dst, int* __restrict__ cnt, int E) {
    int e = blockIdx.x * blockDim.x + threadIdx.x;
    if (e < E) atomicAdd(&cnt[dst[e]], 1);
}
__global__ void scan_block_kernel(const int* __restrict__ in, int* __restrict__ out,
                                  int* __restrict__ bsums, int n) {
    __shared__ int sh[SCAN_BLK];
    int i = blockIdx.x * SCAN_BLK + threadIdx.x;
    sh[threadIdx.x] = (i < n) ? in[i] : 0;
    __syncthreads();
#pragma unroll
    for (int off = 1; off < SCAN_BLK; off <<= 1) {
        int t = (threadIdx.x >= off) ? sh[threadIdx.x - off] : 0;
        __syncthreads();
        sh[threadIdx.x] += t;
        __syncthreads();
    }
    if (i < n) out[i] = sh[threadIdx.x];
    if (threadIdx.x == SCAN_BLK - 1) bsums[blockIdx.x] = sh[threadIdx.x];
}
__global__ void scan_sums_kernel(int* __restrict__ bsums, int nb) {
    __shared__ int sh[MAX_SCAN_BLOCKS];
    int v = (threadIdx.x < nb) ? bsums[threadIdx.x] : 0;
    sh[threadIdx.x] = v;
    __syncthreads();
#pragma unroll
    for (int off = 1; off < MAX_SCAN_BLOCKS; off <<= 1) {
        int t = (threadIdx.x >= off) ? sh[threadIdx.x - off] : 0;
        __syncthreads();
        sh[threadIdx.x] += t;
        __syncthreads();
    }
    if (threadIdx.x < nb) bsums[threadIdx.x] = sh[threadIdx.x];
}
__global__ void finalize_scan_kernel(const int* __restrict__ inc, const int* __restrict__ bsums,
                                     const int* __restrict__ cnt, int* __restrict__ rowptr,
                                     int* __restrict__ cursor, float* __restrict__ dinv, int n) {
    int i = blockIdx.x * SCAN_BLK + threadIdx.x;
    if (i >= n) return;
    int add = (blockIdx.x > 0) ? bsums[blockIdx.x - 1] : 0;
    int v = inc[i] + add;
    rowptr[i + 1] = v;
    cursor[i] = v - cnt[i];
    dinv[i] = rsqrtf(1.0f + (float)cnt[i]);
    if (i == 0) rowptr[0] = 0;
}
__global__ void fill_cols_kernel(const int* __restrict__ src, const int* __restrict__ dst,
                                 int* __restrict__ cursor, int* __restrict__ cols, int E) {
    int e = blockIdx.x * blockDim.x + threadIdx.x;
    if (e < E) {
        int pos = atomicAdd(&cursor[dst[e]], 1);
        cols[pos] = src[e];
    }
}

// ---------------------------------------------------------------------------
// bf16 2-term split helpers
// ---------------------------------------------------------------------------
__device__ __forceinline__ void split2(float v, __nv_bfloat16& h, __nv_bfloat16& l) {
    h = __float2bfloat16(v);
    l = __float2bfloat16(v - __bfloat162float(h));
}

__global__ void split_kernel(const float* __restrict__ x,
                             __nv_bfloat16* __restrict__ hi,
                             __nv_bfloat16* __restrict__ lo, int n4) {
    int i = blockIdx.x * blockDim.x + threadIdx.x;
    if (i >= n4) return;
    float4 v = *(const float4*)(x + (size_t)i * 4);
    __nv_bfloat16 h0, l0, h1, l1, h2, l2, h3, l3;
    split2(v.x, h0, l0); split2(v.y, h1, l1); split2(v.z, h2, l2); split2(v.w, h3, l3);
    __nv_bfloat162 hh0 = {h0, h1}, hh1 = {h2, h3};
    __nv_bfloat162 ll0 = {l0, l1}, ll1 = {l2, l3};
    *(uint2*)(hi + (size_t)i * 4) = make_uint2(*(uint32_t*)&hh0, *(uint32_t*)&hh1);
    *(uint2*)(lo + (size_t)i * 4) = make_uint2(*(uint32_t*)&ll0, *(uint32_t*)&ll1);
}

// All three W [128(k), BN(n)] -> Wt hi/lo [BN][128], one launch.
// layer offsets in elements: L1 at 0 (BN=128), L2 at 16384 (128), L3 at 32768 (64).
__global__ void wsplit_all_kernel(const float* __restrict__ W1,
                                  const float* __restrict__ W2,
                                  const float* __restrict__ W3,
                                  __nv_bfloat16* __restrict__ hi,
                                  __nv_bfloat16* __restrict__ lo) {
    int i = blockIdx.x * blockDim.x + threadIdx.x;   // 0 .. 40959
    if (i >= 128 * (128 + 128 + 64)) return;
    const float* W;
    int BN, base;
    if (i < 16384)      { W = W1; BN = 128; base = 0; }
    else if (i < 32768) { W = W2; BN = 128; base = 16384; }
    else                { W = W3; BN = 64;  base = 32768; }
    int li = i - base;
    int nrow = li >> 7;
    int k = li & 127;
    float v = W[(size_t)k * BN + nrow];
    __nv_bfloat16 h, l;
    split2(v, h, l);
    hi[i] = h; lo[i] = l;
}

// ---------------------------------------------------------------------------
// mma.sync bf16-split GEMM with ldmatrix fragment loads.
// One CTA = 128 x BN x 128. 256 threads (8 warps: 4 along M, 2 along N).
// SMEM rows padded to 136 bf16: 272B row stride -> 16*row mod 128 distinct,
// so every 8-address ldmatrix phase is conflict-free.
// ---------------------------------------------------------------------------
#define SMPITCH 136

__device__ __forceinline__ void mma16816(float* c, const uint32_t* a, const uint32_t* b) {
    asm volatile(
        "mma.sync.aligned.m16n8k16.row.col.f32.bf16.bf16.f32 "
        "{%0,%1,%2,%3}, {%4,%5,%6,%7}, {%8,%9}, {%0,%1,%2,%3};"
        : "+f"(c[0]), "+f"(c[1]), "+f"(c[2]), "+f"(c[3])
        : "r"(a[0]), "r"(a[1]), "r"(a[2]), "r"(a[3]), "r"(b[0]), "r"(b[1]));
}

__device__ __forceinline__ void ldsm_x4(uint32_t& r0, uint32_t& r1, uint32_t& r2, uint32_t& r3,
                                        uint32_t addr) {
    asm volatile("ldmatrix.sync.aligned.m8n8.x4.shared.b16 {%0,%1,%2,%3}, [%4];"
                 : "=r"(r0), "=r"(r1), "=r"(r2), "=r"(r3) : "r"(addr));
}

template <int BN>
__global__ __launch_bounds__(256, 1) void gemm_mma_kernel(
    const __nv_bfloat16* __restrict__ Ah, const __nv_bfloat16* __restrict__ Al,
    const __nv_bfloat16* __restrict__ Wh, const __nv_bfloat16* __restrict__ Wl,
    const float* __restrict__ dinv, float* __restrict__ G, int N)
{
    constexpr int NT = BN / 16;          // n-tiles (8 wide) per warp: 8 or 4
    extern __shared__ __nv_bfloat16 sm[];
    __nv_bfloat16* sAh = sm;
    __nv_bfloat16* sAl = sAh + 128 * SMPITCH;
    __nv_bfloat16* sWh = sAl + 128 * SMPITCH;
    __nv_bfloat16* sWl = sWh + BN * SMPITCH;

    const int tid = threadIdx.x;
    const int wid = tid >> 5;
    const int lane = tid & 31;
    const int warp_m = wid & 3;
    const int warp_n = wid >> 2;
    const int g = lane >> 2;
    const int tg = lane & 3;
    const int block_row = blockIdx.x * 128;

    // ---- stage tiles ----
    for (int i = tid; i < 128 * 16; i += 256) {
        int row = i >> 4, c = i & 15;
        int grow = block_row + row;
        uint4 vh = make_uint4(0, 0, 0, 0), vl = make_uint4(0, 0, 0, 0);
        if (grow < N) {
            vh = *(const uint4*)(Ah + (size_t)grow * 128 + c * 8);
            vl = *(const uint4*)(Al + (size_t)grow * 128 + c * 8);
        }
        *(uint4*)(sAh + row * SMPITCH + c * 8) = vh;
        *(uint4*)(sAl + row * SMPITCH + c * 8) = vl;
    }
    for (int i = tid; i < BN * 16; i += 256) {
        int row = i >> 4, c = i & 15;
        *(uint4*)(sWh + row * SMPITCH + c * 8) = *(const uint4*)(Wh + (size_t)row * 128 + c * 8);
        *(uint4*)(sWl + row * SMPITCH + c * 8) = *(const uint4*)(Wl + (size_t)row * 128 + c * 8);
    }
    __syncthreads();

    // ldmatrix lane address components
    const uint32_t uAh = (uint32_t)__cvta_generic_to_shared(sAh);
    const uint32_t uAl = (uint32_t)__cvta_generic_to_shared(sAl);
    const uint32_t uWh = (uint32_t)__cvta_generic_to_shared(sWh);
    const uint32_t uWl = (uint32_t)__cvta_generic_to_shared(sWl);
    // A: row = warp_m*32 + i*16 + (lane&15); kcol = kb + ((lane>>4)<<3)
    const int a_row = warp_m * 32 + (lane & 15);
    const int a_koff = (lane >> 4) << 3;
    // B: row = warp_n*(BN/2) + jp*16 + (lane&7) + ((lane>>4)<<3); kcol = kb + (((lane>>3)&1)<<3)
    const int b_row = warp_n * (BN / 2) + (lane & 7) + ((lane >> 4) << 3);
    const int b_koff = ((lane >> 3) & 1) << 3;

    float acc[2][NT][4];
#pragma unroll
    for (int i = 0; i < 2; i++)
#pragma unroll
        for (int j = 0; j < NT; j++)
#pragma unroll
            for (int q = 0; q < 4; q++) acc[i][j][q] = 0.f;

#pragma unroll
    for (int ks = 0; ks < 8; ks++) {
        const int kb = ks * 16;
        uint32_t ah[2][4], al[2][4];
#pragma unroll
        for (int i = 0; i < 2; i++) {
            uint32_t off = (uint32_t)(((a_row + i * 16) * SMPITCH + kb + a_koff) * 2);
            ldsm_x4(ah[i][0], ah[i][1], ah[i][2], ah[i][3], uAh + off);
            ldsm_x4(al[i][0], al[i][1], al[i][2], al[i][3], uAl + off);
        }
#pragma unroll
        for (int jp = 0; jp < NT / 2; jp++) {
            uint32_t off = (uint32_t)(((b_row + jp * 16) * SMPITCH + kb + b_koff) * 2);
            uint32_t bh[4], bl[4];
            ldsm_x4(bh[0], bh[1], bh[2], bh[3], uWh + off);
            ldsm_x4(bl[0], bl[1], bl[2], bl[3], uWl + off);
#pragma unroll
            for (int i = 0; i < 2; i++) {
                mma16816(acc[i][2 * jp + 0], ah[i], bh + 0);
                mma16816(acc[i][2 * jp + 0], al[i], bh + 0);
                mma16816(acc[i][2 * jp + 0], ah[i], bl + 0);
                mma16816(acc[i][2 * jp + 1], ah[i], bh + 2);
                mma16816(acc[i][2 * jp + 1], al[i], bh + 2);
                mma16816(acc[i][2 * jp + 1], ah[i], bl + 2);
            }
        }
    }

    // ---- epilogue: scale by dinv[row], store fp32 ----
#pragma unroll
    for (int i = 0; i < 2; i++) {
        int r0 = block_row + warp_m * 32 + i * 16 + g;
        int r1 = r0 + 8;
        float s0 = (r0 < N) ? dinv[r0] : 0.f;
        float s1 = (r1 < N) ? dinv[r1] : 0.f;
#pragma unroll
        for (int j = 0; j < NT; j++) {
            int c = warp_n * (BN / 2) + j * 8 + tg * 2;
            if (r0 < N) {
                float2 v = make_float2(acc[i][j][0] * s0, acc[i][j][1] * s0);
                *(float2*)(G + (size_t)r0 * BN + c) = v;
            }
            if (r1 < N) {
                float2 v = make_float2(acc[i][j][2] * s1, acc[i][j][3] * s1);
                *(float2*)(G + (size_t)r1 * BN + c) = v;
            }
        }
    }
}

// ---------------------------------------------------------------------------
// Fused gather + finalize (DIM=128): warp per node, unroll-8 dual accumulators,
// writes bf16 hi/lo for the next GEMM.
// ---------------------------------------------------------------------------
__global__ __launch_bounds__(256) void gather128_split_kernel(
    const float* __restrict__ G, const int* __restrict__ rowptr,
    const int* __restrict__ cols, const float* __restrict__ dinv,
    const float* __restrict__ b,
    __nv_bfloat16* __restrict__ outh, __nv_bfloat16* __restrict__ outl, int N)
{
    int warp = (blockIdx.x * blockDim.x + threadIdx.x) >> 5;
    int lane = threadIdx.x & 31;
    if (warp >= N) return;
    const int fl = lane * 4;
    int beg = rowptr[warp];
    int end = rowptr[warp + 1];

    float4 acc0 = *(const float4*)(G + (size_t)warp * 128 + fl);  // self-loop
    float4 acc1 = make_float4(0.f, 0.f, 0.f, 0.f);

    int e = beg;
    for (; e + 8 <= end; e += 8) {
        int c0 = cols[e + 0], c1 = cols[e + 1], c2 = cols[e + 2], c3 = cols[e + 3];
        int c4 = cols[e + 4], c5 = cols[e + 5], c6 = cols[e + 6], c7 = cols[e + 7];
        float4 v0 = *(const float4*)(G + (size_t)c0 * 128 + fl);
        float4 v1 = *(const float4*)(G + (size_t)c1 * 128 + fl);
        float4 v2 = *(const float4*)(G + (size_t)c2 * 128 + fl);
        float4 v3 = *(const float4*)(G + (size_t)c3 * 128 + fl);
        float4 v4 = *(const float4*)(G + (size_t)c4 * 128 + fl);
        float4 v5 = *(const float4*)(G + (size_t)c5 * 128 + fl);
        float4 v6 = *(const float4*)(G + (size_t)c6 * 128 + fl);
        float4 v7 = *(const float4*)(G + (size_t)c7 * 128 + fl);
        acc0.x += (v0.x + v1.x) + (v2.x + v3.x);
        acc0.y += (v0.y + v1.y) + (v2.y + v3.y);
        acc0.z += (v0.z + v1.z) + (v2.z + v3.z);
        acc0.w += (v0.w + v1.w) + (v2.w + v3.w);
        acc1.x += (v4.x + v5.x) + (v6.x + v7.x);
        acc1.y += (v4.y + v5.y) + (v6.y + v7.y);
        acc1.z += (v4.z + v5.z) + (v6.z + v7.z);
        acc1.w += (v4.w + v5.w) + (v6.w + v7.w);
    }
    for (; e < end; e++) {
        int c = cols[e];
        float4 v = *(const float4*)(G + (size_t)c * 128 + fl);
        acc1.x += v.x; acc1.y += v.y; acc1.z += v.z; acc1.w += v.w;
    }
    float4 acc = make_float4(acc0.x + acc1.x, acc0.y + acc1.y,
                             acc0.z + acc1.z, acc0.w + acc1.w);

    float di = dinv[warp];
    float4 bb = *(const float4*)(b + fl);
    float4 o;
    o.x = fmaxf(fmaf(di, acc.x, bb.x), 0.f);
    o.y = fmaxf(fmaf(di, acc.y, bb.y), 0.f);
    o.z = fmaxf(fmaf(di, acc.z, bb.z), 0.f);
    o.w = fmaxf(fmaf(di, acc.w, bb.w), 0.f);

    __nv_bfloat16 h0, l0, h1, l1, h2, l2, h3, l3;
    split2(o.x, h0, l0); split2(o.y, h1, l1); split2(o.z, h2, l2); split2(o.w, h3, l3);
    __nv_bfloat162 hh0 = {h0, h1}, hh1 = {h2, h3};
    __nv_bfloat162 ll0 = {l0, l1}, ll1 = {l2, l3};
    *(uint2*)(outh + (size_t)warp * 128 + fl) = make_uint2(*(uint32_t*)&hh0, *(uint32_t*)&hh1);
    *(uint2*)(outl + (size_t)warp * 128 + fl) = make_uint2(*(uint32_t*)&ll0, *(uint32_t*)&ll1);
}

// DIM=64, final layer: fp32 output, no activation.
__global__ __launch_bounds__(256) void gather64_kernel(
    const float* __restrict__ G, const int* __restrict__ rowptr,
    const int* __restrict__ cols, const float* __restrict__ dinv,
    const float* __restrict__ b, float* __restrict__ out, int N)
{
    int warp = (blockIdx.x * blockDim.x + threadIdx.x) >> 5;
    int lane = threadIdx.x & 31;
    if (warp >= N) return;
    const int fl = lane * 2;
    int beg = rowptr[warp];
    int end = rowptr[warp + 1];

    float2 acc0 = *(const float2*)(G + (size_t)warp * 64 + fl);
    float2 acc1 = make_float2(0.f, 0.f);

    int e = beg;
    for (; e + 8 <= end; e += 8) {
        int c0 = cols[e + 0], c1 = cols[e + 1], c2 = cols[e + 2], c3 = cols[e + 3];
        int c4 = cols[e + 4], c5 = cols[e + 5], c6 = cols[e + 6], c7 = cols[e + 7];
        float2 v0 = *(const float2*)(G + (size_t)c0 * 64 + fl);
        float2 v1 = *(const float2*)(G + (size_t)c1 * 64 + fl);
        float2 v2 = *(const float2*)(G + (size_t)c2 * 64 + fl);
        float2 v3 = *(const float2*)(G + (size_t)c3 * 64 + fl);
        float2 v4 = *(const float2*)(G + (size_t)c4 * 64 + fl);
        float2 v5 = *(const float2*)(G + (size_t)c5 * 64 + fl);
        float2 v6 = *(const float2*)(G + (size_t)c6 * 64 + fl);
        float2 v7 = *(const float2*)(G + (size_t)c7 * 64 + fl);
        acc0.x += (v0.x + v1.x) + (v2.x + v3.x);
        acc0.y += (v0.y + v1.y) + (v2.y + v3.y);
        acc1.x += (v4.x + v5.x) + (v6.x + v7.x);
        acc1.y += (v4.y + v5.y) + (v6.y + v7.y);
    }
    for (; e < end; e++) {
        int c = cols[e];
        float2 v = *(const float2*)(G + (size_t)c * 64 + fl);
        acc1.x += v.x; acc1.y += v.y;
    }
    float2 acc = make_float2(acc0.x + acc1.x, acc0.y + acc1.y);

    float di = dinv[warp];
    float2 bb = *(const float2*)(b + fl);
    float2 o;
    o.x = fmaf(di, acc.x, bb.x);
    o.y = fmaf(di, acc.y, bb.y);
    *(float2*)(out + (size_t)warp * 64 + fl) = o;
}

// ---------------------------------------------------------------------------
static inline int cdiv(int a, int b) { return (a + b - 1) / b; }

extern "C" void kernel_launch(void* const* d_in, const int* in_sizes, int n_in,
                              void* d_out, int out_size)
{
    const float* x  = (const float*)d_in[0];
    const int*   ei = (const int*)d_in[1];
    const float* W1 = (const float*)d_in[2];
    const float* b1 = (const float*)d_in[3];
    const float* W2 = (const float*)d_in[4];
    const float* b2 = (const float*)d_in[5];
    const float* W3 = (const float*)d_in[6];
    const float* b3 = (const float*)d_in[7];
    float* out = (float*)d_out;

    const int N = in_sizes[0] / 128;
    const int E = in_sizes[1] / 2;
    const int* src = ei;
    const int* dst = ei + E;

    float *g, *dinv;
    __nv_bfloat16 *ah, *al, *wh, *wl;
    int *cnt, *inc, *bsum, *rowptr, *cursor, *cols;
    cudaGetSymbolAddress((void**)&g, g_buf);
    cudaGetSymbolAddress((void**)&ah, ah_buf);
    cudaGetSymbolAddress((void**)&al, al_buf);
    cudaGetSymbolAddress((void**)&wh, wh_buf);
    cudaGetSymbolAddress((void**)&wl, wl_buf);
    cudaGetSymbolAddress((void**)&dinv, dinv_buf);
    cudaGetSymbolAddress((void**)&cnt, cnt_buf);
    cudaGetSymbolAddress((void**)&inc, inc_buf);
    cudaGetSymbolAddress((void**)&bsum, bsum_buf);
    cudaGetSymbolAddress((void**)&rowptr, rowptr_buf);
    cudaGetSymbolAddress((void**)&cursor, cursor_buf);
    cudaGetSymbolAddress((void**)&cols, cols_buf);

    constexpr int SMEM_128 = (2 * 128 + 2 * 128) * SMPITCH * 2;  // 139264
    constexpr int SMEM_64  = (2 * 128 + 2 * 64) * SMPITCH * 2;   // 104448
    cudaFuncSetAttribute(gemm_mma_kernel<128>, cudaFuncAttributeMaxDynamicSharedMemorySize, SMEM_128);
    cudaFuncSetAttribute(gemm_mma_kernel<64>,  cudaFuncAttributeMaxDynamicSharedMemorySize, SMEM_64);

    // ---------------- CSR build + dinv ----------------
    const int nb = cdiv(N, SCAN_BLK);
    zero_int_kernel<<<cdiv(N, 256), 256>>>(cnt, N);
    count_kernel<<<cdiv(E, 256), 256>>>(dst, cnt, E);
    scan_block_kernel<<<nb, SCAN_BLK>>>(cnt, inc, bsum, N);
    scan_sums_kernel<<<1, MAX_SCAN_BLOCKS>>>(bsum, nb);
    finalize_scan_kernel<<<nb, SCAN_BLK>>>(inc, bsum, cnt, rowptr, cursor, dinv, N);
    fill_cols_kernel<<<cdiv(E, 256), 256>>>(src, dst, cursor, cols, E);

    // ---------------- input / weight splits ----------------
    split_kernel<<<cdiv(N * 32, 256), 256>>>(x, ah, al, N * 32);
    wsplit_all_kernel<<<cdiv(128 * 320, 256), 256>>>(W1, W2, W3, wh, wl);

    const int gemm_blocks = cdiv(N, 128);
    const int gather_blocks = cdiv(N * 32, 256);

    // ---------------- layer 1 (128 -> 128, ReLU) ----------------
    gemm_mma_kernel<128><<<gemm_blocks, 256, SMEM_128>>>(ah, al, wh, wl, dinv, g, N);
    gather128_split_kernel<<<gather_blocks, 256>>>(g, rowptr, cols, dinv, b1, ah, al, N);

    // ---------------- layer 2 (128 -> 128, ReLU) ----------------
    gemm_mma_kernel<128><<<gemm_blocks, 256, SMEM_128>>>(ah, al, wh + 16384, wl + 16384, dinv, g, N);
    gather128_split_kernel<<<gather_blocks, 256>>>(g, rowptr, cols, dinv, b2, ah, al, N);

    // ---------------- layer 3 (128 -> 64, no activation) ----------------
    gemm_mma_kernel<64><<<gemm_blocks, 256, SMEM_64>>>(ah, al, wh + 2 * 16384, wl + 2 * 16384, dinv, g, N);
    gather64_kernel<<<gather_blocks, 256>>>(g, rowptr, cols, dinv, b3, out, N);
}

// round 8
// speedup vs baseline: 4.5107x; 1.1402x over previous
#include <cuda_runtime.h>
#include <cuda_bf16.h>
#include <cuda_fp16.h>
#include <cstdint>

// ---------------------------------------------------------------------------
// GCN 3-layer encoder. CSR gather (fp16 messages) + mma.sync bf16-split GEMM.
//   g = (X @ W) * dinv   (stored fp16)
//   out[i] = dinv[i]*(sum_{j in N(i)} g[j] + g[i]) + b  (+ReLU)
// ---------------------------------------------------------------------------

#define MAX_NODES 100000
#define MAX_EDGES 1600000
#define SCAN_BLK  1024
#define MAX_SCAN_BLOCKS 128

__device__ __half        g_buf[MAX_NODES * 128];
__device__ __nv_bfloat16 ah_buf[MAX_NODES * 128];
__device__ __nv_bfloat16 al_buf[MAX_NODES * 128];
__device__ __nv_bfloat16 wh_buf[3 * 128 * 128];   // transposed [n][k]
__device__ __nv_bfloat16 wl_buf[3 * 128 * 128];
__device__ float dinv_buf[MAX_NODES];
__device__ int   cnt_buf[MAX_NODES];
__device__ int   inc_buf[MAX_NODES];
__device__ int   bsum_buf[MAX_SCAN_BLOCKS];
__device__ int   rowptr_buf[MAX_NODES + 1];
__device__ int   cursor_buf[MAX_NODES];
__device__ int   cols_buf[MAX_EDGES];

// ---------------------------------------------------------------------------
// CSR build helpers
// ---------------------------------------------------------------------------
__global__ void zero_int_kernel(int* __restrict__ p, int n) {
    int i = blockIdx.x * blockDim.x + threadIdx.x;
    if (i < n) p[i] = 0;
}
__global__ void count_kernel(const int* __restrict__ dst, int* __restrict__ cnt, int E) {
    int e = blockIdx.x * blockDim.x + threadIdx.x;
    if (e < E) atomicAdd(&cnt[dst[e]], 1);
}
__global__ void scan_block_kernel(const int* __restrict__ in, int* __restrict__ out,
                                  int* __restrict__ bsums, int n) {
    __shared__ int sh[SCAN_BLK];
    int i = blockIdx.x * SCAN_BLK + threadIdx.x;
    sh[threadIdx.x] = (i < n) ? in[i] : 0;
    __syncthreads();
#pragma unroll
    for (int off = 1; off < SCAN_BLK; off <<= 1) {
        int t = (threadIdx.x >= off) ? sh[threadIdx.x - off] : 0;
        __syncthreads();
        sh[threadIdx.x] += t;
        __syncthreads();
    }
    if (i < n) out[i] = sh[threadIdx.x];
    if (threadIdx.x == SCAN_BLK - 1) bsums[blockIdx.x] = sh[threadIdx.x];
}
__global__ void scan_sums_kernel(int* __restrict__ bsums, int nb) {
    __shared__ int sh[MAX_SCAN_BLOCKS];
    int v = (threadIdx.x < nb) ? bsums[threadIdx.x] : 0;
    sh[threadIdx.x] = v;
    __syncthreads();
#pragma unroll
    for (int off = 1; off < MAX_SCAN_BLOCKS; off <<= 1) {
        int t = (threadIdx.x >= off) ? sh[threadIdx.x - off] : 0;
        __syncthreads();
        sh[threadIdx.x] += t;
        __syncthreads();
    }
    if (threadIdx.x < nb) bsums[threadIdx.x] = sh[threadIdx.x];
}
__global__ void finalize_scan_kernel(const int* __restrict__ inc, const int* __restrict__ bsums,
                                     const int* __restrict__ cnt, int* __restrict__ rowptr,
                                     int* __restrict__ cursor, float* __restrict__ dinv, int n) {
    int i = blockIdx.x * SCAN_BLK + threadIdx.x;
    if (i >= n) return;
    int add = (blockIdx.x > 0) ? bsums[blockIdx.x - 1] : 0;
    int v = inc[i] + add;
    rowptr[i + 1] = v;
    cursor[i] = v - cnt[i];
    dinv[i] = rsqrtf(1.0f + (float)cnt[i]);
    if (i == 0) rowptr[0] = 0;
}
__global__ void fill_cols_kernel(const int* __restrict__ src, const int* __restrict__ dst,
                                 int* __restrict__ cursor, int* __restrict__ cols, int E) {
    int e = blockIdx.x * blockDim.x + threadIdx.x;
    if (e < E) {
        int pos = atomicAdd(&cursor[dst[e]], 1);
        cols[pos] = src[e];
    }
}

// ---------------------------------------------------------------------------
// bf16 2-term split helpers
// ---------------------------------------------------------------------------
__device__ __forceinline__ void split2(float v, __nv_bfloat16& h, __nv_bfloat16& l) {
    h = __float2bfloat16(v);
    l = __float2bfloat16(v - __bfloat162float(h));
}

__global__ void split_kernel(const float* __restrict__ x,
                             __nv_bfloat16* __restrict__ hi,
                             __nv_bfloat16* __restrict__ lo, int n4) {
    int i = blockIdx.x * blockDim.x + threadIdx.x;
    if (i >= n4) return;
    float4 v = *(const float4*)(x + (size_t)i * 4);
    __nv_bfloat16 h0, l0, h1, l1, h2, l2, h3, l3;
    split2(v.x, h0, l0); split2(v.y, h1, l1); split2(v.z, h2, l2); split2(v.w, h3, l3);
    __nv_bfloat162 hh0 = {h0, h1}, hh1 = {h2, h3};
    __nv_bfloat162 ll0 = {l0, l1}, ll1 = {l2, l3};
    *(uint2*)(hi + (size_t)i * 4) = make_uint2(*(uint32_t*)&hh0, *(uint32_t*)&hh1);
    *(uint2*)(lo + (size_t)i * 4) = make_uint2(*(uint32_t*)&ll0, *(uint32_t*)&ll1);
}

// All three W [128(k), BN(n)] -> Wt hi/lo [BN][128], one launch.
__global__ void wsplit_all_kernel(const float* __restrict__ W1,
                                  const float* __restrict__ W2,
                                  const float* __restrict__ W3,
                                  __nv_bfloat16* __restrict__ hi,
                                  __nv_bfloat16* __restrict__ lo) {
    int i = blockIdx.x * blockDim.x + threadIdx.x;   // 0 .. 40959
    if (i >= 128 * (128 + 128 + 64)) return;
    const float* W;
    int BN, base;
    if (i < 16384)      { W = W1; BN = 128; base = 0; }
    else if (i < 32768) { W = W2; BN = 128; base = 16384; }
    else                { W = W3; BN = 64;  base = 32768; }
    int li = i - base;
    int nrow = li >> 7;
    int k = li & 127;
    float v = W[(size_t)k * BN + nrow];
    __nv_bfloat16 h, l;
    split2(v, h, l);
    hi[i] = h; lo[i] = l;
}

// ---------------------------------------------------------------------------
// mma.sync bf16-split GEMM with ldmatrix fragment loads.
// One CTA = 128 x BN x 128. 256 threads (8 warps: 4 along M, 2 along N).
// Epilogue stores fp16 (half2) messages scaled by dinv[row].
// ---------------------------------------------------------------------------
#define SMPITCH 136

__device__ __forceinline__ void mma16816(float* c, const uint32_t* a, const uint32_t* b) {
    asm volatile(
        "mma.sync.aligned.m16n8k16.row.col.f32.bf16.bf16.f32 "
        "{%0,%1,%2,%3}, {%4,%5,%6,%7}, {%8,%9}, {%0,%1,%2,%3};"
        : "+f"(c[0]), "+f"(c[1]), "+f"(c[2]), "+f"(c[3])
        : "r"(a[0]), "r"(a[1]), "r"(a[2]), "r"(a[3]), "r"(b[0]), "r"(b[1]));
}

__device__ __forceinline__ void ldsm_x4(uint32_t& r0, uint32_t& r1, uint32_t& r2, uint32_t& r3,
                                        uint32_t addr) {
    asm volatile("ldmatrix.sync.aligned.m8n8.x4.shared.b16 {%0,%1,%2,%3}, [%4];"
                 : "=r"(r0), "=r"(r1), "=r"(r2), "=r"(r3) : "r"(addr));
}

template <int BN>
__global__ __launch_bounds__(256, 1) void gemm_mma_kernel(
    const __nv_bfloat16* __restrict__ Ah, const __nv_bfloat16* __restrict__ Al,
    const __nv_bfloat16* __restrict__ Wh, const __nv_bfloat16* __restrict__ Wl,
    const float* __restrict__ dinv, __half* __restrict__ G, int N)
{
    constexpr int NT = BN / 16;
    extern __shared__ __nv_bfloat16 sm[];
    __nv_bfloat16* sAh = sm;
    __nv_bfloat16* sAl = sAh + 128 * SMPITCH;
    __nv_bfloat16* sWh = sAl + 128 * SMPITCH;
    __nv_bfloat16* sWl = sWh + BN * SMPITCH;

    const int tid = threadIdx.x;
    const int wid = tid >> 5;
    const int lane = tid & 31;
    const int warp_m = wid & 3;
    const int warp_n = wid >> 2;
    const int g = lane >> 2;
    const int tg = lane & 3;
    const int block_row = blockIdx.x * 128;

    // ---- stage tiles ----
    for (int i = tid; i < 128 * 16; i += 256) {
        int row = i >> 4, c = i & 15;
        int grow = block_row + row;
        uint4 vh = make_uint4(0, 0, 0, 0), vl = make_uint4(0, 0, 0, 0);
        if (grow < N) {
            vh = *(const uint4*)(Ah + (size_t)grow * 128 + c * 8);
            vl = *(const uint4*)(Al + (size_t)grow * 128 + c * 8);
        }
        *(uint4*)(sAh + row * SMPITCH + c * 8) = vh;
        *(uint4*)(sAl + row * SMPITCH + c * 8) = vl;
    }
    for (int i = tid; i < BN * 16; i += 256) {
        int row = i >> 4, c = i & 15;
        *(uint4*)(sWh + row * SMPITCH + c * 8) = *(const uint4*)(Wh + (size_t)row * 128 + c * 8);
        *(uint4*)(sWl + row * SMPITCH + c * 8) = *(const uint4*)(Wl + (size_t)row * 128 + c * 8);
    }
    __syncthreads();

    const uint32_t uAh = (uint32_t)__cvta_generic_to_shared(sAh);
    const uint32_t uAl = (uint32_t)__cvta_generic_to_shared(sAl);
    const uint32_t uWh = (uint32_t)__cvta_generic_to_shared(sWh);
    const uint32_t uWl = (uint32_t)__cvta_generic_to_shared(sWl);
    const int a_row = warp_m * 32 + (lane & 15);
    const int a_koff = (lane >> 4) << 3;
    const int b_row = warp_n * (BN / 2) + (lane & 7) + ((lane >> 4) << 3);
    const int b_koff = ((lane >> 3) & 1) << 3;

    float acc[2][NT][4];
#pragma unroll
    for (int i = 0; i < 2; i++)
#pragma unroll
        for (int j = 0; j < NT; j++)
#pragma unroll
            for (int q = 0; q < 4; q++) acc[i][j][q] = 0.f;

#pragma unroll
    for (int ks = 0; ks < 8; ks++) {
        const int kb = ks * 16;
        uint32_t ah[2][4], al[2][4];
#pragma unroll
        for (int i = 0; i < 2; i++) {
            uint32_t off = (uint32_t)(((a_row + i * 16) * SMPITCH + kb + a_koff) * 2);
            ldsm_x4(ah[i][0], ah[i][1], ah[i][2], ah[i][3], uAh + off);
            ldsm_x4(al[i][0], al[i][1], al[i][2], al[i][3], uAl + off);
        }
#pragma unroll
        for (int jp = 0; jp < NT / 2; jp++) {
            uint32_t off = (uint32_t)(((b_row + jp * 16) * SMPITCH + kb + b_koff) * 2);
            uint32_t bh[4], bl[4];
            ldsm_x4(bh[0], bh[1], bh[2], bh[3], uWh + off);
            ldsm_x4(bl[0], bl[1], bl[2], bl[3], uWl + off);
#pragma unroll
            for (int i = 0; i < 2; i++) {
                mma16816(acc[i][2 * jp + 0], ah[i], bh + 0);
                mma16816(acc[i][2 * jp + 0], al[i], bh + 0);
                mma16816(acc[i][2 * jp + 0], ah[i], bl + 0);
                mma16816(acc[i][2 * jp + 1], ah[i], bh + 2);
                mma16816(acc[i][2 * jp + 1], al[i], bh + 2);
                mma16816(acc[i][2 * jp + 1], ah[i], bl + 2);
            }
        }
    }

    // ---- epilogue: scale by dinv[row], store fp16 half2 ----
#pragma unroll
    for (int i = 0; i < 2; i++) {
        int r0 = block_row + warp_m * 32 + i * 16 + g;
        int r1 = r0 + 8;
        float s0 = (r0 < N) ? dinv[r0] : 0.f;
        float s1 = (r1 < N) ? dinv[r1] : 0.f;
#pragma unroll
        for (int j = 0; j < NT; j++) {
            int c = warp_n * (BN / 2) + j * 8 + tg * 2;
            if (r0 < N) {
                __half2 v = __floats2half2_rn(acc[i][j][0] * s0, acc[i][j][1] * s0);
                *(__half2*)(G + (size_t)r0 * BN + c) = v;
            }
            if (r1 < N) {
                __half2 v = __floats2half2_rn(acc[i][j][2] * s1, acc[i][j][3] * s1);
                *(__half2*)(G + (size_t)r1 * BN + c) = v;
            }
        }
    }
}

// ---------------------------------------------------------------------------
// Fused gather + finalize (DIM=128): warp per node, fp16 message reads,
// unroll-8 dual accumulators, writes bf16 hi/lo for the next GEMM.
// ---------------------------------------------------------------------------
__device__ __forceinline__ float4 h4_to_f4(uint2 raw) {
    __half2 p0 = *(__half2*)&raw.x;
    __half2 p1 = *(__half2*)&raw.y;
    float2 f0 = __half22float2(p0);
    float2 f1 = __half22float2(p1);
    return make_float4(f0.x, f0.y, f1.x, f1.y);
}

__global__ __launch_bounds__(256) void gather128_split_kernel(
    const __half* __restrict__ G, const int* __restrict__ rowptr,
    const int* __restrict__ cols, const float* __restrict__ dinv,
    const float* __restrict__ b,
    __nv_bfloat16* __restrict__ outh, __nv_bfloat16* __restrict__ outl, int N)
{
    int warp = (blockIdx.x * blockDim.x + threadIdx.x) >> 5;
    int lane = threadIdx.x & 31;
    if (warp >= N) return;
    const int fl = lane * 4;
    int beg = rowptr[warp];
    int end = rowptr[warp + 1];

    float4 acc0 = h4_to_f4(*(const uint2*)(G + (size_t)warp * 128 + fl));  // self
    float4 acc1 = make_float4(0.f, 0.f, 0.f, 0.f);

    int e = beg;
    for (; e + 8 <= end; e += 8) {
        int c0 = cols[e + 0], c1 = cols[e + 1], c2 = cols[e + 2], c3 = cols[e + 3];
        int c4 = cols[e + 4], c5 = cols[e + 5], c6 = cols[e + 6], c7 = cols[e + 7];
        float4 v0 = h4_to_f4(*(const uint2*)(G + (size_t)c0 * 128 + fl));
        float4 v1 = h4_to_f4(*(const uint2*)(G + (size_t)c1 * 128 + fl));
        float4 v2 = h4_to_f4(*(const uint2*)(G + (size_t)c2 * 128 + fl));
        float4 v3 = h4_to_f4(*(const uint2*)(G + (size_t)c3 * 128 + fl));
        float4 v4 = h4_to_f4(*(const uint2*)(G + (size_t)c4 * 128 + fl));
        float4 v5 = h4_to_f4(*(const uint2*)(G + (size_t)c5 * 128 + fl));
        float4 v6 = h4_to_f4(*(const uint2*)(G + (size_t)c6 * 128 + fl));
        float4 v7 = h4_to_f4(*(const uint2*)(G + (size_t)c7 * 128 + fl));
        acc0.x += (v0.x + v1.x) + (v2.x + v3.x);
        acc0.y += (v0.y + v1.y) + (v2.y + v3.y);
        acc0.z += (v0.z + v1.z) + (v2.z + v3.z);
        acc0.w += (v0.w + v1.w) + (v2.w + v3.w);
        acc1.x += (v4.x + v5.x) + (v6.x + v7.x);
        acc1.y += (v4.y + v5.y) + (v6.y + v7.y);
        acc1.z += (v4.z + v5.z) + (v6.z + v7.z);
        acc1.w += (v4.w + v5.w) + (v6.w + v7.w);
    }
    for (; e < end; e++) {
        int c = cols[e];
        float4 v = h4_to_f4(*(const uint2*)(G + (size_t)c * 128 + fl));
        acc1.x += v.x; acc1.y += v.y; acc1.z += v.z; acc1.w += v.w;
    }
    float4 acc = make_float4(acc0.x + acc1.x, acc0.y + acc1.y,
                             acc0.z + acc1.z, acc0.w + acc1.w);

    float di = dinv[warp];
    float4 bb = *(const float4*)(b + fl);
    float4 o;
    o.x = fmaxf(fmaf(di, acc.x, bb.x), 0.f);
    o.y = fmaxf(fmaf(di, acc.y, bb.y), 0.f);
    o.z = fmaxf(fmaf(di, acc.z, bb.z), 0.f);
    o.w = fmaxf(fmaf(di, acc.w, bb.w), 0.f);

    __nv_bfloat16 h0, l0, h1, l1, h2, l2, h3, l3;
    split2(o.x, h0, l0); split2(o.y, h1, l1); split2(o.z, h2, l2); split2(o.w, h3, l3);
    __nv_bfloat162 hh0 = {h0, h1}, hh1 = {h2, h3};
    __nv_bfloat162 ll0 = {l0, l1}, ll1 = {l2, l3};
    *(uint2*)(outh + (size_t)warp * 128 + fl) = make_uint2(*(uint32_t*)&hh0, *(uint32_t*)&hh1);
    *(uint2*)(outl + (size_t)warp * 128 + fl) = make_uint2(*(uint32_t*)&ll0, *(uint32_t*)&ll1);
}

// DIM=64, final layer: fp16 message reads, fp32 output, no activation.
__global__ __launch_bounds__(256) void gather64_kernel(
    const __half* __restrict__ G, const int* __restrict__ rowptr,
    const int* __restrict__ cols, const float* __restrict__ dinv,
    const float* __restrict__ b, float* __restrict__ out, int N)
{
    int warp = (blockIdx.x * blockDim.x + threadIdx.x) >> 5;
    int lane = threadIdx.x & 31;
    if (warp >= N) return;
    const int fl = lane * 2;
    int beg = rowptr[warp];
    int end = rowptr[warp + 1];

    float2 acc0 = __half22float2(*(const __half2*)(G + (size_t)warp * 64 + fl));
    float2 acc1 = make_float2(0.f, 0.f);

    int e = beg;
    for (; e + 8 <= end; e += 8) {
        int c0 = cols[e + 0], c1 = cols[e + 1], c2 = cols[e + 2], c3 = cols[e + 3];
        int c4 = cols[e + 4], c5 = cols[e + 5], c6 = cols[e + 6], c7 = cols[e + 7];
        float2 v0 = __half22float2(*(const __half2*)(G + (size_t)c0 * 64 + fl));
        float2 v1 = __half22float2(*(const __half2*)(G + (size_t)c1 * 64 + fl));
        float2 v2 = __half22float2(*(const __half2*)(G + (size_t)c2 * 64 + fl));
        float2 v3 = __half22float2(*(const __half2*)(G + (size_t)c3 * 64 + fl));
        float2 v4 = __half22float2(*(const __half2*)(G + (size_t)c4 * 64 + fl));
        float2 v5 = __half22float2(*(const __half2*)(G + (size_t)c5 * 64 + fl));
        float2 v6 = __half22float2(*(const __half2*)(G + (size_t)c6 * 64 + fl));
        float2 v7 = __half22float2(*(const __half2*)(G + (size_t)c7 * 64 + fl));
        acc0.x += (v0.x + v1.x) + (v2.x + v3.x);
        acc0.y += (v0.y + v1.y) + (v2.y + v3.y);
        acc1.x += (v4.x + v5.x) + (v6.x + v7.x);
        acc1.y += (v4.y + v5.y) + (v6.y + v7.y);
    }
    for (; e < end; e++) {
        int c = cols[e];
        float2 v = __half22float2(*(const __half2*)(G + (size_t)c * 64 + fl));
        acc1.x += v.x; acc1.y += v.y;
    }
    float2 acc = make_float2(acc0.x + acc1.x, acc0.y + acc1.y);

    float di = dinv[warp];
    float2 bb = *(const float2*)(b + fl);
    float2 o;
    o.x = fmaf(di, acc.x, bb.x);
    o.y = fmaf(di, acc.y, bb.y);
    *(float2*)(out + (size_t)warp * 64 + fl) = o;
}

// ---------------------------------------------------------------------------
static inline int cdiv(int a, int b) { return (a + b - 1) / b; }

extern "C" void kernel_launch(void* const* d_in, const int* in_sizes, int n_in,
                              void* d_out, int out_size)
{
    const float* x  = (const float*)d_in[0];
    const int*   ei = (const int*)d_in[1];
    const float* W1 = (const float*)d_in[2];
    const float* b1 = (const float*)d_in[3];
    const float* W2 = (const float*)d_in[4];
    const float* b2 = (const float*)d_in[5];
    const float* W3 = (const float*)d_in[6];
    const float* b3 = (const float*)d_in[7];
    float* out = (float*)d_out;

    const int N = in_sizes[0] / 128;
    const int E = in_sizes[1] / 2;
    const int* src = ei;
    const int* dst = ei + E;

    float *dinv;
    __half* g;
    __nv_bfloat16 *ah, *al, *wh, *wl;
    int *cnt, *inc, *bsum, *rowptr, *cursor, *cols;
    cudaGetSymbolAddress((void**)&g, g_buf);
    cudaGetSymbolAddress((void**)&ah, ah_buf);
    cudaGetSymbolAddress((void**)&al, al_buf);
    cudaGetSymbolAddress((void**)&wh, wh_buf);
    cudaGetSymbolAddress((void**)&wl, wl_buf);
    cudaGetSymbolAddress((void**)&dinv, dinv_buf);
    cudaGetSymbolAddress((void**)&cnt, cnt_buf);
    cudaGetSymbolAddress((void**)&inc, inc_buf);
    cudaGetSymbolAddress((void**)&bsum, bsum_buf);
    cudaGetSymbolAddress((void**)&rowptr, rowptr_buf);
    cudaGetSymbolAddress((void**)&cursor, cursor_buf);
    cudaGetSymbolAddress((void**)&cols, cols_buf);

    constexpr int SMEM_128 = (2 * 128 + 2 * 128) * SMPITCH * 2;  // 139264
    constexpr int SMEM_64  = (2 * 128 + 2 * 64) * SMPITCH * 2;   // 104448
    cudaFuncSetAttribute(gemm_mma_kernel<128>, cudaFuncAttributeMaxDynamicSharedMemorySize, SMEM_128);
    cudaFuncSetAttribute(gemm_mma_kernel<64>,  cudaFuncAttributeMaxDynamicSharedMemorySize, SMEM_64);

    // ---------------- CSR build + dinv ----------------
    const int nb = cdiv(N, SCAN_BLK);
    zero_int_kernel<<<cdiv(N, 256), 256>>>(cnt, N);
    count_kernel<<<cdiv(E, 256), 256>>>(dst, cnt, E);
    scan_block_kernel<<<nb, SCAN_BLK>>>(cnt, inc, bsum, N);
    scan_sums_kernel<<<1, MAX_SCAN_BLOCKS>>>(bsum, nb);
    finalize_scan_kernel<<<nb, SCAN_BLK>>>(inc, bsum, cnt, rowptr, cursor, dinv, N);
    fill_cols_kernel<<<cdiv(E, 256), 256>>>(src, dst, cursor, cols, E);

    // ---------------- input / weight splits ----------------
    split_kernel<<<cdiv(N * 32, 256), 256>>>(x, ah, al, N * 32);
    wsplit_all_kernel<<<cdiv(128 * 320, 256), 256>>>(W1, W2, W3, wh, wl);

    const int gemm_blocks = cdiv(N, 128);
    const int gather_blocks = cdiv(N * 32, 256);

    // ---------------- layer 1 (128 -> 128, ReLU) ----------------
    gemm_mma_kernel<128><<<gemm_blocks, 256, SMEM_128>>>(ah, al, wh, wl, dinv, g, N);
    gather128_split_kernel<<<gather_blocks, 256>>>(g, rowptr, cols, dinv, b1, ah, al, N);

    // ---------------- layer 2 (128 -> 128, ReLU) ----------------
    gemm_mma_kernel<128><<<gemm_blocks, 256, SMEM_128>>>(ah, al, wh + 16384, wl + 16384, dinv, g, N);
    gather128_split_kernel<<<gather_blocks, 256>>>(g, rowptr, cols, dinv, b2, ah, al, N);

    // ---------------- layer 3 (128 -> 64, no activation) ----------------
    gemm_mma_kernel<64><<<gemm_blocks, 256, SMEM_64>>>(ah, al, wh + 2 * 16384, wl + 2 * 16384, dinv, g, N);
    gather64_kernel<<<gather_blocks, 256>>>(g, rowptr, cols, dinv, b3, out, N);
}